// round 4
// baseline (speedup 1.0000x reference)
#include <cuda_runtime.h>
#include <cuda_bf16.h>
#include <math.h>
#include <stdint.h>

#define BDIM 64
#define TDIM 4096
#define CDIM 64
#define HDIM 64
#define WDIM 64
#define CONDD 16
#define HID 128
#define INDIM 81
#define K0P 96
#define NTOK 128
#define NTHREADS 256
#define PITCH 136
#define PITCH_U32 68
#define S_MAX 1.5f
#define NCHUNK_TOT 15

#define NTOT (BDIM * TDIM)
#define ZSIZE ((size_t)NTOT * 2)

__device__ float g_wT[(size_t)BDIM * HDIM * WDIM * CDIM];
__device__ __align__(16) __nv_bfloat16 g_W0h[4 * K0P * HID];
__device__ __align__(16) __nv_bfloat16 g_W0l[4 * K0P * HID];
__device__ __align__(16) __nv_bfloat16 g_W1h[12 * HID * HID];
__device__ __align__(16) __nv_bfloat16 g_W1l[12 * HID * HID];

__device__ __forceinline__ float silu_f(float z) {
    return __fdividef(z, 1.0f + __expf(-z));
}
__device__ __forceinline__ void ldsm_x4(uint32_t d[4], uint32_t saddr) {
    asm volatile("ldmatrix.sync.aligned.m8n8.x4.shared.b16 {%0,%1,%2,%3}, [%4];\n"
        : "=r"(d[0]), "=r"(d[1]), "=r"(d[2]), "=r"(d[3]) : "r"(saddr));
}
__device__ __forceinline__ void ldsm_x4_t(uint32_t d[4], uint32_t saddr) {
    asm volatile("ldmatrix.sync.aligned.m8n8.x4.trans.shared.b16 {%0,%1,%2,%3}, [%4];\n"
        : "=r"(d[0]), "=r"(d[1]), "=r"(d[2]), "=r"(d[3]) : "r"(saddr));
}
__device__ __forceinline__ void mma_bf16(float c[4], const uint32_t a[4],
                                         uint32_t b0, uint32_t b1) {
    asm volatile(
        "mma.sync.aligned.m16n8k16.row.col.f32.bf16.bf16.f32 "
        "{%0,%1,%2,%3}, {%4,%5,%6,%7}, {%8,%9}, {%0,%1,%2,%3};\n"
        : "+f"(c[0]), "+f"(c[1]), "+f"(c[2]), "+f"(c[3])
        : "r"(a[0]), "r"(a[1]), "r"(a[2]), "r"(a[3]), "r"(b0), "r"(b1));
}
__device__ __forceinline__ void cp_async16(uint32_t saddr, const void* gaddr) {
    asm volatile("cp.async.cg.shared.global [%0], [%1], 16;\n" :: "r"(saddr), "l"(gaddr));
}
template <int N>
__device__ __forceinline__ void cp_wait() {
    asm volatile("cp.async.wait_group %0;\n" :: "n"(N));
}
__device__ __forceinline__ void cp_commit() {
    asm volatile("cp.async.commit_group;\n");
}

__device__ __forceinline__ void split_store_pair(uint32_t* H, uint32_t* L,
                                                 int row, int n0, float a, float b) {
    __nv_bfloat16 ah = __float2bfloat16_rn(a);
    __nv_bfloat16 bh = __float2bfloat16_rn(b);
    float ar = a - __bfloat162float(ah);
    float br = b - __bfloat162float(bh);
    __nv_bfloat162 hp = __halves2bfloat162(ah, bh);
    __nv_bfloat162 lp = __halves2bfloat162(__float2bfloat16_rn(ar), __float2bfloat16_rn(br));
    H[row * PITCH_U32 + (n0 >> 1)] = *reinterpret_cast<uint32_t*>(&hp);
    L[row * PITCH_U32 + (n0 >> 1)] = *reinterpret_cast<uint32_t*>(&lp);
}

__device__ __forceinline__ void chunk_src(int net, int g,
                                          const __nv_bfloat16** srcH,
                                          const __nv_bfloat16** srcL) {
    if (g < 3) {
        int off = net * K0P * HID + g * 32 * HID;
        *srcH = g_W0h + off;
        *srcL = g_W0l + off;
    } else {
        int gg = g - 3;
        int gi = net * 3 + (gg >> 2);
        int off = gi * HID * HID + (gg & 3) * 32 * HID;
        *srcH = g_W1h + off;
        *srcL = g_W1l + off;
    }
}

__device__ __forceinline__ void issue_chunk(int net, int g,
                                            uint32_t WbH_s, uint32_t WbL_s, int tid) {
    const __nv_bfloat16 *srcH, *srcL;
    chunk_src(net, g, &srcH, &srcL);
#pragma unroll
    for (int q = 0; q < 2; ++q) {
        int i = tid + q * NTHREADS;
        int k = i >> 4, cc = i & 15;
        uint32_t dof = (uint32_t)((k * 17 + cc) * 16);
        cp_async16(WbH_s + dof, (const char*)srcH + (size_t)i * 16);
        cp_async16(WbL_s + dof, (const char*)srcL + (size_t)i * 16);
    }
    cp_commit();
}

__global__ void prep_kernel(const float* __restrict__ W0,
                            const float* __restrict__ W1,
                            float* __restrict__ out) {
    int idx = blockIdx.x * blockDim.x + threadIdx.x;
    if (idx < 4 * K0P * HID) {
        int i = idx / (K0P * HID);
        int r = idx % (K0P * HID);
        int k = r >> 7, nn = r & 127;
        float v = 0.0f;
        if (k <= 80) {
            int korig = (k < 80) ? (k + 1) : 0;
            v = W0[(i * HID + nn) * INDIM + korig];
        }
        __nv_bfloat16 h = __float2bfloat16_rn(v);
        g_W0h[idx] = h;
        g_W0l[idx] = __float2bfloat16_rn(v - __bfloat162float(h));
    }
    if (idx < 12 * HID * HID) {
        int g = idx >> 14;
        int r = idx & 16383;
        int k = r >> 7, nn = r & 127;
        float v = W1[(g * HID + nn) * HID + k];
        __nv_bfloat16 h = __float2bfloat16_rn(v);
        g_W1h[idx] = h;
        g_W1l[idx] = __float2bfloat16_rn(v - __bfloat162float(h));
    }
    if (idx < BDIM) out[ZSIZE + idx] = 0.0f;
}

__global__ void transpose_w_kernel(const float* __restrict__ w) {
    __shared__ float tile[64][65];
    int by = blockIdx.x;
    int b = by / HDIM, y = by % HDIM;
    int tid = threadIdx.x;
    for (int i = tid; i < 64 * 64; i += NTHREADS) {
        int c = i >> 6, xq = i & 63;
        tile[c][xq] = w[(((size_t)b * CDIM + c) * HDIM + y) * WDIM + xq];
    }
    __syncthreads();
    for (int i = tid; i < 64 * 64; i += NTHREADS) {
        int xq = i >> 6, c = i & 63;
        g_wT[(((size_t)b * HDIM + y) * WDIM + xq) * CDIM + c] = tile[c][xq];
    }
}

template <int PHASE>
__global__ __launch_bounds__(NTHREADS, 2)
void phase_kernel(const float* __restrict__ x,
                  const float* __restrict__ cond,
                  const float* __restrict__ b0g,
                  const float* __restrict__ b1g,
                  const float* __restrict__ W2g,
                  const float* __restrict__ b2g,
                  float* __restrict__ out) {
    extern __shared__ char smraw[];
    __nv_bfloat16* actH = (__nv_bfloat16*)smraw;
    __nv_bfloat16* actL = actH + NTOK * PITCH;
    __nv_bfloat16* Wb   = actL + NTOK * PITCH;          // 2 bufs x (H 32*136 + L 32*136)
    float* sArr = (float*)(Wb + 4 * 32 * PITCH);
    float* tArr = sArr + NTOK;
    float* w2sm = tArr + NTOK;

    const int tid = threadIdx.x;
    const int lane = tid & 31;
    const int wid = tid >> 5;
    const int tokBase = (wid & 1) * 64;
    const int nBase = (wid >> 1) * 32;
    const int nbase = blockIdx.x * NTOK;
    const int b = nbase >> 12;

    uint32_t actH_s = (uint32_t)__cvta_generic_to_shared(actH);
    uint32_t actL_s = (uint32_t)__cvta_generic_to_shared(actL);
    uint32_t Wb_s   = (uint32_t)__cvta_generic_to_shared(Wb);
    uint32_t* actH_u = (uint32_t*)actH;
    uint32_t* actL_u = (uint32_t*)actL;

    const int r8 = lane & 7;
    const int gA = (lane >> 3) & 1;
    const int gB = lane >> 4;

    for (int half = 0; half < 2; ++half) {
        const int net = ((PHASE == 1) ? 0 : 2) + half;

        issue_chunk(net, 0, Wb_s, Wb_s + 32 * PITCH * 2, tid);

        // ---- gather: 2 threads per token, 32 channels each ----
        {
            int tk = tid >> 1;
            int hf = tid & 1;
            int n = nbase + tk;
            float zx, zy, zkeep;
            if (PHASE == 1) { zx = x[2 * n]; zy = x[2 * n + 1]; zkeep = zy; }
            else            { zx = out[2 * n]; zy = x[2 * n + 1]; zkeep = zx; }
            float ix = zx * 63.0f, iy = zy * 63.0f;
            float ix0 = floorf(ix), iy0 = floorf(iy);
            float wx1 = ix - ix0, wx0 = 1.0f - wx1;
            float wy1 = iy - iy0, wy0 = 1.0f - wy1;
            float acc[32];
#pragma unroll
            for (int c = 0; c < 32; c++) acc[c] = 0.0f;
#pragma unroll
            for (int corner = 0; corner < 4; corner++) {
                int dx = corner & 1, dy = corner >> 1;
                float xx = ix0 + (float)dx, yy = iy0 + (float)dy;
                bool valid = (xx >= 0.0f) && (xx <= 63.0f) && (yy >= 0.0f) && (yy <= 63.0f);
                if (valid) {
                    float wgt = (dx ? wx1 : wx0) * (dy ? wy1 : wy0);
                    int xc = (int)xx, yc = (int)yy;
                    const float4* gp = (const float4*)(g_wT +
                        (((size_t)b * HDIM + yc) * WDIM + xc) * CDIM + hf * 32);
#pragma unroll
                    for (int q = 0; q < 8; q++) {
                        float4 v = gp[q];
                        acc[q * 4 + 0] += wgt * v.x;
                        acc[q * 4 + 1] += wgt * v.y;
                        acc[q * 4 + 2] += wgt * v.z;
                        acc[q * 4 + 3] += wgt * v.w;
                    }
                }
            }
#pragma unroll
            for (int c = 0; c < 16; c++)
                split_store_pair(actH_u, actL_u, tk, hf * 32 + 2 * c,
                                 acc[2 * c], acc[2 * c + 1]);
            if (hf == 0) {
#pragma unroll
                for (int j = 0; j < 8; j++) {
                    float c0 = cond[b * CONDD + 2 * j];
                    float c1 = cond[b * CONDD + 2 * j + 1];
                    split_store_pair(actH_u, actL_u, tk, 64 + 2 * j, c0, c1);
                }
            } else {
                split_store_pair(actH_u, actL_u, tk, 80, zkeep, 0.0f);
#pragma unroll
                for (int q = 41; q < 48; q++) {
                    actH_u[tk * PITCH_U32 + q] = 0u;
                    actL_u[tk * PITCH_U32 + q] = 0u;
                }
            }
        }

        int g = 0;
        for (int l = 0; l < 4; ++l) {
            const float* bias = (l == 0) ? (b0g + net * HID)
                                         : (b1g + (net * 3 + (l - 1)) * HID);
            const int nc = (l == 0) ? 3 : 4;

            float accA[2][4][4], accB[2][4][4];
#pragma unroll
            for (int mi = 0; mi < 2; mi++)
#pragma unroll
                for (int nj = 0; nj < 4; nj++)
#pragma unroll
                    for (int q = 0; q < 4; q++) { accA[mi][nj][q] = 0.0f; accB[mi][nj][q] = 0.0f; }

            for (int ch = 0; ch < nc; ++ch, ++g) {
                __syncthreads();
                if (g + 1 < NCHUNK_TOT) {
                    uint32_t base = Wb_s + (uint32_t)(((g + 1) & 1) * (32 * PITCH * 4));
                    issue_chunk(net, g + 1, base, base + 32 * PITCH * 2, tid);
                    cp_wait<1>();
                } else {
                    cp_wait<0>();
                }
                __syncthreads();

                uint32_t WH_s = Wb_s + (uint32_t)((g & 1) * (32 * PITCH * 4));
                uint32_t WL_s = WH_s + 32 * PITCH * 2;
#pragma unroll
                for (int ks = 0; ks < 2; ++ks) {
                    int colA = ch * 32 + ks * 16 + gB * 8;
                    uint32_t aH[4][4], aL[4][4];
#pragma unroll
                    for (int mi = 0; mi < 4; mi++) {
                        uint32_t off = (uint32_t)(((tokBase + mi * 16 + r8 + gA * 8) * PITCH + colA) * 2);
                        ldsm_x4(aH[mi], actH_s + off);
                        ldsm_x4(aL[mi], actL_s + off);
                    }
#pragma unroll
                    for (int nj = 0; nj < 2; nj++) {
                        uint32_t bH[4], bL[4];
                        uint32_t off = (uint32_t)(((ks * 16 + r8 + gA * 8) * PITCH +
                                                   nBase + nj * 16 + gB * 8) * 2);
                        ldsm_x4_t(bH, WH_s + off);
                        ldsm_x4_t(bL, WL_s + off);
#pragma unroll
                        for (int h2 = 0; h2 < 2; h2++) {
                            uint32_t w0 = (h2 == 0) ? bH[0] : bH[2];
                            uint32_t w1 = (h2 == 0) ? bH[1] : bH[3];
                            uint32_t v0 = (h2 == 0) ? bL[0] : bL[2];
                            uint32_t v1 = (h2 == 0) ? bL[1] : bL[3];
                            float* c0 = accA[0][nj * 2 + h2];
                            mma_bf16(c0, aH[0], w0, w1);
                            mma_bf16(c0, aH[0], v0, v1);
                            mma_bf16(c0, aL[0], w0, w1);
                            float* c1 = accA[1][nj * 2 + h2];
                            mma_bf16(c1, aH[1], w0, w1);
                            mma_bf16(c1, aH[1], v0, v1);
                            mma_bf16(c1, aL[1], w0, w1);
                            float* c2 = accB[0][nj * 2 + h2];
                            mma_bf16(c2, aH[2], w0, w1);
                            mma_bf16(c2, aH[2], v0, v1);
                            mma_bf16(c2, aL[2], w0, w1);
                            float* c3 = accB[1][nj * 2 + h2];
                            mma_bf16(c3, aH[3], w0, w1);
                            mma_bf16(c3, aH[3], v0, v1);
                            mma_bf16(c3, aL[3], w0, w1);
                        }
                    }
                }
            }
            __syncthreads();

#pragma unroll
            for (int mi = 0; mi < 2; mi++) {
                int row0 = tokBase + mi * 16 + (lane >> 2);
#pragma unroll
                for (int n8 = 0; n8 < 4; n8++) {
                    int n0 = nBase + n8 * 8 + (lane & 3) * 2;
                    float2 bb = *(const float2*)&bias[n0];
                    float* d = accA[mi][n8];
                    split_store_pair(actH_u, actL_u, row0, n0,
                                     silu_f(d[0] + bb.x), silu_f(d[1] + bb.y));
                    split_store_pair(actH_u, actL_u, row0 + 8, n0,
                                     silu_f(d[2] + bb.x), silu_f(d[3] + bb.y));
                    float* e = accB[mi][n8];
                    split_store_pair(actH_u, actL_u, row0 + 32, n0,
                                     silu_f(e[0] + bb.x), silu_f(e[1] + bb.y));
                    split_store_pair(actH_u, actL_u, row0 + 40, n0,
                                     silu_f(e[2] + bb.x), silu_f(e[3] + bb.y));
                }
            }
        }

        if (tid < HID) w2sm[tid] = W2g[net * HID + tid];
        __syncthreads();
        if (tid < NTOK) {
            float sum = 0.0f;
            int rowOff = tid * PITCH_U32;
#pragma unroll 8
            for (int i = 0; i < 64; ++i) {
                uint32_t hp = actH_u[rowOff + i];
                uint32_t lp = actL_u[rowOff + i];
                __nv_bfloat162 hv = *reinterpret_cast<__nv_bfloat162*>(&hp);
                __nv_bfloat162 lv = *reinterpret_cast<__nv_bfloat162*>(&lp);
                float v0 = __bfloat162float(hv.x) + __bfloat162float(lv.x);
                float v1 = __bfloat162float(hv.y) + __bfloat162float(lv.y);
                sum += v0 * w2sm[2 * i] + v1 * w2sm[2 * i + 1];
            }
            float* dst = (half == 0) ? sArr : tArr;
            dst[tid] = sum + b2g[net];
        }
        __syncthreads();
    }

    if (tid < NTOK) {
        int n = nbase + tid;
        float s = tanhf(sArr[tid]) * S_MAX;
        float t = tArr[tid];
        float zold = (PHASE == 1) ? x[2 * n] : x[2 * n + 1];
        out[2 * n + ((PHASE == 1) ? 0 : 1)] = zold * expf(s) + t;
        sArr[tid] = s;
    }
    __syncthreads();
    if (tid < 32) {
        float v = sArr[tid] + sArr[tid + 32] + sArr[tid + 64] + sArr[tid + 96];
#pragma unroll
        for (int off = 16; off > 0; off >>= 1) v += __shfl_down_sync(0xffffffffu, v, off);
        if (tid == 0) atomicAdd(out + ZSIZE + b, v);
    }
}

extern "C" void kernel_launch(void* const* d_in, const int* in_sizes, int n_in,
                              void* d_out, int out_size) {
    const float* x    = (const float*)d_in[0];
    const float* w    = (const float*)d_in[1];
    const float* cond = (const float*)d_in[2];
    const float* W0   = (const float*)d_in[3];
    const float* b0   = (const float*)d_in[4];
    const float* W1   = (const float*)d_in[5];
    const float* b1   = (const float*)d_in[6];
    const float* W2   = (const float*)d_in[7];
    const float* b2   = (const float*)d_in[8];
    float* out = (float*)d_out;

    const size_t smem = (size_t)(2 * NTOK * PITCH + 4 * 32 * PITCH) * 2 +
                        (size_t)(2 * NTOK + HID) * 4;
    cudaFuncSetAttribute(phase_kernel<1>, cudaFuncAttributeMaxDynamicSharedMemorySize, (int)smem);
    cudaFuncSetAttribute(phase_kernel<2>, cudaFuncAttributeMaxDynamicSharedMemorySize, (int)smem);

    prep_kernel<<<768, NTHREADS>>>(W0, W1, out);
    transpose_w_kernel<<<BDIM * HDIM, NTHREADS>>>(w);
    phase_kernel<1><<<NTOT / NTOK, NTHREADS, smem>>>(x, cond, b0, b1, W2, b2, out);
    phase_kernel<2><<<NTOT / NTOK, NTHREADS, smem>>>(x, cond, b0, b1, W2, b2, out);
}

// round 10
// speedup vs baseline: 1.0510x; 1.0510x over previous
#include <cuda_runtime.h>
#include <cuda_bf16.h>
#include <math.h>
#include <stdint.h>

#define BDIM 64
#define TDIM 4096
#define CDIM 64
#define HDIM 64
#define WDIM 64
#define CONDD 16
#define HID 128
#define INDIM 81
#define NTOK 128
#define NTHREADS 256
#define PITCH 136
#define PITCH_U32 68
#define S_MAX 1.5f

#define NTOT (BDIM * TDIM)
#define ZSIZE ((size_t)NTOT * 2)

// ---------------- device scratch ----------------
__device__ float g_wT[(size_t)BDIM * HDIM * WDIM * CDIM];   // [b][y][x][c]
// B fragments in mma.sync lane order: [img(16)][ks(8)][n8(16)][lane(32)][reg(2)]
__device__ __align__(16) uint32_t g_WfH[16 * 8 * 16 * 64];
__device__ __align__(16) uint32_t g_WfL[16 * 8 * 16 * 64];

__device__ __forceinline__ float silu_f(float z) {
    return __fdividef(z, 1.0f + __expf(-z));
}
__device__ __forceinline__ void ldsm_x4(uint32_t d[4], uint32_t saddr) {
    asm volatile("ldmatrix.sync.aligned.m8n8.x4.shared.b16 {%0,%1,%2,%3}, [%4];\n"
        : "=r"(d[0]), "=r"(d[1]), "=r"(d[2]), "=r"(d[3]) : "r"(saddr));
}
__device__ __forceinline__ void mma_bf16(float c[4], const uint32_t a[4],
                                         uint32_t b0, uint32_t b1) {
    asm volatile(
        "mma.sync.aligned.m16n8k16.row.col.f32.bf16.bf16.f32 "
        "{%0,%1,%2,%3}, {%4,%5,%6,%7}, {%8,%9}, {%0,%1,%2,%3};\n"
        : "+f"(c[0]), "+f"(c[1]), "+f"(c[2]), "+f"(c[3])
        : "r"(a[0]), "r"(a[1]), "r"(a[2]), "r"(a[3]), "r"(b0), "r"(b1));
}

__device__ __forceinline__ void split_store_pair(uint32_t* H, uint32_t* L,
                                                 int row, int n0, float a, float b) {
    __nv_bfloat16 ah = __float2bfloat16_rn(a);
    __nv_bfloat16 bh = __float2bfloat16_rn(b);
    float ar = a - __bfloat162float(ah);
    float br = b - __bfloat162float(bh);
    __nv_bfloat162 hp = __halves2bfloat162(ah, bh);
    __nv_bfloat162 lp = __halves2bfloat162(__float2bfloat16_rn(ar), __float2bfloat16_rn(br));
    H[row * PITCH_U32 + (n0 >> 1)] = *reinterpret_cast<uint32_t*>(&hp);
    L[row * PITCH_U32 + (n0 >> 1)] = *reinterpret_cast<uint32_t*>(&lp);
}

// ---------------- prep: weights -> mma fragment order (bf16 hi/lo) ----------
__global__ void prep_kernel(const float* __restrict__ W0,
                            const float* __restrict__ W1,
                            float* __restrict__ out) {
    int idx = blockIdx.x * blockDim.x + threadIdx.x;   // 0..262143
    if (idx < 16 * 8 * 16 * 64) {                      // 131072 u32 entries
        int reg  = idx & 1;
        int lane = (idx >> 1) & 31;
        int n8   = (idx >> 6) & 15;
        int ks   = (idx >> 10) & 7;
        int img  = idx >> 13;                          // net*4 + l
        int net = img >> 2, l = img & 3;
        int n  = n8 * 8 + (lane >> 2);
        int k0 = ks * 16 + (lane & 3) * 2 + reg * 8;
        float v0 = 0.0f, v1 = 0.0f;
        if (l == 0) {
            // act k-order: [lf(0..63) | cond(64..79) | z(80) | pad]
            if (k0 <= 80)     v0 = W0[(net * HID + n) * INDIM + ((k0 < 80) ? (k0 + 1) : 0)];
            if (k0 + 1 <= 80) v1 = W0[(net * HID + n) * INDIM + ((k0 + 1 < 80) ? (k0 + 2) : 0)];
        } else {
            int g = net * 3 + (l - 1);
            v0 = W1[(g * HID + n) * HID + k0];
            v1 = W1[(g * HID + n) * HID + k0 + 1];
        }
        __nv_bfloat16 h0 = __float2bfloat16_rn(v0);
        __nv_bfloat16 h1 = __float2bfloat16_rn(v1);
        __nv_bfloat162 hp = __halves2bfloat162(h0, h1);
        __nv_bfloat162 lp = __halves2bfloat162(
            __float2bfloat16_rn(v0 - __bfloat162float(h0)),
            __float2bfloat16_rn(v1 - __bfloat162float(h1)));
        g_WfH[idx] = *reinterpret_cast<uint32_t*>(&hp);
        g_WfL[idx] = *reinterpret_cast<uint32_t*>(&lp);
    }
    if (idx < BDIM) out[ZSIZE + idx] = 0.0f;
}

// ---------------- transpose w [B,C,H,W] -> g_wT [B,H,W,C] ----------------
__global__ void transpose_w_kernel(const float* __restrict__ w) {
    __shared__ float tile[64][65];
    int by = blockIdx.x;
    int b = by / HDIM, y = by % HDIM;
    int tid = threadIdx.x;
    for (int i = tid; i < 64 * 64; i += NTHREADS) {
        int c = i >> 6, xq = i & 63;
        tile[c][xq] = w[(((size_t)b * CDIM + c) * HDIM + y) * WDIM + xq];
    }
    __syncthreads();
    for (int i = tid; i < 64 * 64; i += NTHREADS) {
        int xq = i >> 6, c = i & 63;
        g_wT[(((size_t)b * HDIM + y) * WDIM + xq) * CDIM + c] = tile[c][xq];
    }
}

// ---------------- phase kernel ----------------
template <int PHASE>
__global__ __launch_bounds__(NTHREADS, 2)
void phase_kernel(const float* __restrict__ x,
                  const float* __restrict__ cond,
                  const float* __restrict__ b0g,
                  const float* __restrict__ b1g,
                  const float* __restrict__ W2g,
                  const float* __restrict__ b2g,
                  float* __restrict__ out) {
    extern __shared__ char smraw[];
    __nv_bfloat16* actH = (__nv_bfloat16*)smraw;        // 128*136 bf16
    __nv_bfloat16* actL = actH + NTOK * PITCH;          // 128*136 bf16
    float* sArr = (float*)(actL + NTOK * PITCH);
    float* tArr = sArr + NTOK;
    float* w2sm = tArr + NTOK;

    const int tid = threadIdx.x;
    const int lane = tid & 31;
    const int wid = tid >> 5;
    const int tokBase = (wid & 1) * 64;
    const int n8base = (wid >> 1) * 4;        // 4 n8-tiles per warp (32 outs)
    const int nBase = n8base * 8;
    const int nbase = blockIdx.x * NTOK;
    const int b = nbase >> 12;

    uint32_t actH_s = (uint32_t)__cvta_generic_to_shared(actH);
    uint32_t actL_s = (uint32_t)__cvta_generic_to_shared(actL);
    uint32_t* actH_u = (uint32_t*)actH;
    uint32_t* actL_u = (uint32_t*)actL;

    const int r8 = lane & 7;
    const int gA = (lane >> 3) & 1;
    const int gB = lane >> 4;

    for (int half = 0; half < 2; ++half) {
        const int net = ((PHASE == 1) ? 0 : 2) + half;

        // ---- gather: 2 threads per token, 32 channels each ----
        {
            int tk = tid >> 1;
            int hf = tid & 1;
            int n = nbase + tk;
            float zx, zy, zkeep;
            if (PHASE == 1) { zx = x[2 * n]; zy = x[2 * n + 1]; zkeep = zy; }
            else            { zx = out[2 * n]; zy = x[2 * n + 1]; zkeep = zx; }
            float ix = zx * 63.0f, iy = zy * 63.0f;
            float ix0 = floorf(ix), iy0 = floorf(iy);
            float wx1 = ix - ix0, wx0 = 1.0f - wx1;
            float wy1 = iy - iy0, wy0 = 1.0f - wy1;
            float acc[32];
#pragma unroll
            for (int c = 0; c < 32; c++) acc[c] = 0.0f;
#pragma unroll
            for (int corner = 0; corner < 4; corner++) {
                int dx = corner & 1, dy = corner >> 1;
                float xx = ix0 + (float)dx, yy = iy0 + (float)dy;
                if (xx >= 0.0f && xx <= 63.0f && yy >= 0.0f && yy <= 63.0f) {
                    float wgt = (dx ? wx1 : wx0) * (dy ? wy1 : wy0);
                    const float4* gp = (const float4*)(g_wT +
                        (((size_t)b * HDIM + (int)yy) * WDIM + (int)xx) * CDIM + hf * 32);
#pragma unroll
                    for (int q = 0; q < 8; q++) {
                        float4 v = gp[q];
                        acc[q * 4 + 0] += wgt * v.x;
                        acc[q * 4 + 1] += wgt * v.y;
                        acc[q * 4 + 2] += wgt * v.z;
                        acc[q * 4 + 3] += wgt * v.w;
                    }
                }
            }
#pragma unroll
            for (int c = 0; c < 16; c++)
                split_store_pair(actH_u, actL_u, tk, hf * 32 + 2 * c,
                                 acc[2 * c], acc[2 * c + 1]);
            if (hf == 0) {
#pragma unroll
                for (int j = 0; j < 8; j++) {
                    float c0 = cond[b * CONDD + 2 * j];
                    float c1 = cond[b * CONDD + 2 * j + 1];
                    split_store_pair(actH_u, actL_u, tk, 64 + 2 * j, c0, c1);
                }
            } else {
                split_store_pair(actH_u, actL_u, tk, 80, zkeep, 0.0f);
#pragma unroll
                for (int q = 41; q < 48; q++) {
                    actH_u[tk * PITCH_U32 + q] = 0u;
                    actL_u[tk * PITCH_U32 + q] = 0u;
                }
            }
        }
        if (tid < HID) w2sm[tid] = W2g[net * HID + tid];
        __syncthreads();

        // ---- 4 layers, weights LDG'd directly from fragment arrays ----
        for (int l = 0; l < 4; ++l) {
            const int img = net * 4 + l;
            const int ksteps = (l == 0) ? 6 : 8;
            const float* bias = (l == 0) ? (b0g + net * HID)
                                         : (b1g + (net * 3 + (l - 1)) * HID);

            float acc[4][4][4];
#pragma unroll
            for (int mi = 0; mi < 4; mi++)
#pragma unroll
                for (int t = 0; t < 4; t++)
#pragma unroll
                    for (int q = 0; q < 4; q++) acc[mi][t][q] = 0.0f;

            for (int ks = 0; ks < ksteps; ++ks) {
                // B fragments: 4 n8-tiles, hi+lo, LDG.64 each (L1/L2 resident)
                uint2 bh[4], bl[4];
#pragma unroll
                for (int t = 0; t < 4; t++) {
                    int off = (((img * 8 + ks) * 16 + n8base + t) << 6) + lane * 2;
                    bh[t] = *(const uint2*)&g_WfH[off];
                    bl[t] = *(const uint2*)&g_WfL[off];
                }
                int colA = ks * 16 + gB * 8;
#pragma unroll
                for (int mi = 0; mi < 4; mi++) {
                    uint32_t aH[4], aL[4];
                    uint32_t offA = (uint32_t)(((tokBase + mi * 16 + r8 + gA * 8) * PITCH + colA) * 2);
                    ldsm_x4(aH, actH_s + offA);
                    ldsm_x4(aL, actL_s + offA);
#pragma unroll
                    for (int t = 0; t < 4; t++) {
                        float* c4 = acc[mi][t];
                        mma_bf16(c4, aH, bh[t].x, bh[t].y);
                        mma_bf16(c4, aH, bl[t].x, bl[t].y);
                        mma_bf16(c4, aL, bh[t].x, bh[t].y);
                    }
                }
            }
            __syncthreads();   // all act reads done before in-place overwrite

            // epilogue: bias + silu -> split bf16 -> act
#pragma unroll
            for (int t = 0; t < 4; t++) {
                int n0 = nBase + t * 8 + (lane & 3) * 2;
                float2 bb = *(const float2*)&bias[n0];
#pragma unroll
                for (int mi = 0; mi < 4; mi++) {
                    int row0 = tokBase + mi * 16 + (lane >> 2);
                    float* d = acc[mi][t];
                    split_store_pair(actH_u, actL_u, row0, n0,
                                     silu_f(d[0] + bb.x), silu_f(d[1] + bb.y));
                    split_store_pair(actH_u, actL_u, row0 + 8, n0,
                                     silu_f(d[2] + bb.x), silu_f(d[3] + bb.y));
                }
            }
            __syncthreads();
        }

        // ---- final 128 -> 1 dot ----
        if (tid < NTOK) {
            float sum = 0.0f;
            int rowOff = tid * PITCH_U32;
#pragma unroll 8
            for (int i = 0; i < 64; ++i) {
                uint32_t hp = actH_u[rowOff + i];
                uint32_t lp = actL_u[rowOff + i];
                __nv_bfloat162 hv = *reinterpret_cast<__nv_bfloat162*>(&hp);
                __nv_bfloat162 lv = *reinterpret_cast<__nv_bfloat162*>(&lp);
                float v0 = __bfloat162float(hv.x) + __bfloat162float(lv.x);
                float v1 = __bfloat162float(hv.y) + __bfloat162float(lv.y);
                sum += v0 * w2sm[2 * i] + v1 * w2sm[2 * i + 1];
            }
            float* dst = (half == 0) ? sArr : tArr;
            dst[tid] = sum + b2g[net];
        }
        __syncthreads();
    }

    // ---- coupling update + log_det ----
    if (tid < NTOK) {
        int n = nbase + tid;
        float s = tanhf(sArr[tid]) * S_MAX;
        float t = tArr[tid];
        float zold = (PHASE == 1) ? x[2 * n] : x[2 * n + 1];
        out[2 * n + ((PHASE == 1) ? 0 : 1)] = zold * expf(s) + t;
        sArr[tid] = s;
    }
    __syncthreads();
    if (tid < 32) {
        float v = sArr[tid] + sArr[tid + 32] + sArr[tid + 64] + sArr[tid + 96];
#pragma unroll
        for (int off = 16; off > 0; off >>= 1) v += __shfl_down_sync(0xffffffffu, v, off);
        if (tid == 0) atomicAdd(out + ZSIZE + b, v);
    }
}

// ---------------- launch ----------------
extern "C" void kernel_launch(void* const* d_in, const int* in_sizes, int n_in,
                              void* d_out, int out_size) {
    const float* x    = (const float*)d_in[0];
    const float* w    = (const float*)d_in[1];
    const float* cond = (const float*)d_in[2];
    const float* W0   = (const float*)d_in[3];
    const float* b0   = (const float*)d_in[4];
    const float* W1   = (const float*)d_in[5];
    const float* b1   = (const float*)d_in[6];
    const float* W2   = (const float*)d_in[7];
    const float* b2   = (const float*)d_in[8];
    float* out = (float*)d_out;

    const size_t smem = (size_t)(2 * NTOK * PITCH) * 2 +       // actH, actL
                        (size_t)(2 * NTOK + HID) * 4;          // sArr, tArr, w2sm
    cudaFuncSetAttribute(phase_kernel<1>, cudaFuncAttributeMaxDynamicSharedMemorySize, (int)smem);
    cudaFuncSetAttribute(phase_kernel<2>, cudaFuncAttributeMaxDynamicSharedMemorySize, (int)smem);

    prep_kernel<<<1024, NTHREADS>>>(W0, W1, out);
    transpose_w_kernel<<<BDIM * HDIM, NTHREADS>>>(w);
    phase_kernel<1><<<NTOT / NTOK, NTHREADS, smem>>>(x, cond, b0, b1, W2, b2, out);
    phase_kernel<2><<<NTOT / NTOK, NTHREADS, smem>>>(x, cond, b0, b1, W2, b2, out);
}

// round 14
// speedup vs baseline: 1.2353x; 1.1754x over previous
#include <cuda_runtime.h>
#include <cuda_bf16.h>
#include <math.h>
#include <stdint.h>

#define BDIM 64
#define TDIM 4096
#define CDIM 64
#define HDIM 64
#define WDIM 64
#define CONDD 16
#define HID 128
#define INDIM 81
#define NTOK 64
#define NTHREADS 256
#define PITCH2 264            // bf16 row pitch: s cols [0,128), t at [136,264)
#define PITCH2_U32 132
#define TOFF 136              // t-region bf16 col offset
#define S_MAX 1.5f

#define NTOT (BDIM * TDIM)
#define ZSIZE ((size_t)NTOT * 2)

// ---------------- device scratch ----------------
__device__ float g_wT[(size_t)BDIM * HDIM * WDIM * CDIM];   // [b][y][x][c]
// B fragments in mma.sync lane order: [img(16)][ks(8)][n8(16)][lane(32)][reg(2)]
__device__ __align__(16) uint32_t g_WfH[16 * 8 * 16 * 64];
__device__ __align__(16) uint32_t g_WfL[16 * 8 * 16 * 64];

__device__ __forceinline__ float silu_f(float z) {
    return __fdividef(z, 1.0f + __expf(-z));
}
__device__ __forceinline__ void ldsm_x4(uint32_t d[4], uint32_t saddr) {
    asm volatile("ldmatrix.sync.aligned.m8n8.x4.shared.b16 {%0,%1,%2,%3}, [%4];\n"
        : "=r"(d[0]), "=r"(d[1]), "=r"(d[2]), "=r"(d[3]) : "r"(saddr));
}
__device__ __forceinline__ void mma_bf16(float c[4], const uint32_t a[4],
                                         uint32_t b0, uint32_t b1) {
    asm volatile(
        "mma.sync.aligned.m16n8k16.row.col.f32.bf16.bf16.f32 "
        "{%0,%1,%2,%3}, {%4,%5,%6,%7}, {%8,%9}, {%0,%1,%2,%3};\n"
        : "+f"(c[0]), "+f"(c[1]), "+f"(c[2]), "+f"(c[3])
        : "r"(a[0]), "r"(a[1]), "r"(a[2]), "r"(a[3]), "r"(b0), "r"(b1));
}

__device__ __forceinline__ void split_store_pair(uint32_t* H, uint32_t* L,
                                                 int row, int n0, float a, float b) {
    __nv_bfloat16 ah = __float2bfloat16_rn(a);
    __nv_bfloat16 bh = __float2bfloat16_rn(b);
    float ar = a - __bfloat162float(ah);
    float br = b - __bfloat162float(bh);
    __nv_bfloat162 hp = __halves2bfloat162(ah, bh);
    __nv_bfloat162 lp = __halves2bfloat162(__float2bfloat16_rn(ar), __float2bfloat16_rn(br));
    H[row * PITCH2_U32 + (n0 >> 1)] = *reinterpret_cast<uint32_t*>(&hp);
    L[row * PITCH2_U32 + (n0 >> 1)] = *reinterpret_cast<uint32_t*>(&lp);
}

// ---------------- prep: weights -> mma fragment order (bf16 hi/lo) ----------
__global__ void prep_kernel(const float* __restrict__ W0,
                            const float* __restrict__ W1,
                            float* __restrict__ out) {
    int idx = blockIdx.x * blockDim.x + threadIdx.x;   // 0..262143
    if (idx < 16 * 8 * 16 * 64) {
        int reg  = idx & 1;
        int lane = (idx >> 1) & 31;
        int n8   = (idx >> 6) & 15;
        int ks   = (idx >> 10) & 7;
        int img  = idx >> 13;                          // net*4 + l
        int net = img >> 2, l = img & 3;
        int n  = n8 * 8 + (lane >> 2);
        int k0 = ks * 16 + (lane & 3) * 2 + reg * 8;
        float v0 = 0.0f, v1 = 0.0f;
        if (l == 0) {
            // act k-order: [lf(0..63) | cond(64..79) | z(80) | pad]
            if (k0 <= 80)     v0 = W0[(net * HID + n) * INDIM + ((k0 < 80) ? (k0 + 1) : 0)];
            if (k0 + 1 <= 80) v1 = W0[(net * HID + n) * INDIM + ((k0 + 1 < 80) ? (k0 + 2) : 0)];
        } else {
            int g = net * 3 + (l - 1);
            v0 = W1[(g * HID + n) * HID + k0];
            v1 = W1[(g * HID + n) * HID + k0 + 1];
        }
        __nv_bfloat16 h0 = __float2bfloat16_rn(v0);
        __nv_bfloat16 h1 = __float2bfloat16_rn(v1);
        __nv_bfloat162 hp = __halves2bfloat162(h0, h1);
        __nv_bfloat162 lp = __halves2bfloat162(
            __float2bfloat16_rn(v0 - __bfloat162float(h0)),
            __float2bfloat16_rn(v1 - __bfloat162float(h1)));
        g_WfH[idx] = *reinterpret_cast<uint32_t*>(&hp);
        g_WfL[idx] = *reinterpret_cast<uint32_t*>(&lp);
    }
    if (idx < BDIM) out[ZSIZE + idx] = 0.0f;
}

// ---------------- transpose w [B,C,H,W] -> g_wT [B,H,W,C] ----------------
__global__ void transpose_w_kernel(const float* __restrict__ w) {
    __shared__ float tile[64][65];
    int by = blockIdx.x;
    int b = by / HDIM, y = by % HDIM;
    int tid = threadIdx.x;
    for (int i = tid; i < 64 * 64; i += NTHREADS) {
        int c = i >> 6, xq = i & 63;
        tile[c][xq] = w[(((size_t)b * CDIM + c) * HDIM + y) * WDIM + xq];
    }
    __syncthreads();
    for (int i = tid; i < 64 * 64; i += NTHREADS) {
        int xq = i >> 6, c = i & 63;
        g_wT[(((size_t)b * HDIM + y) * WDIM + xq) * CDIM + c] = tile[c][xq];
    }
}

// ---------------- phase kernel: s-net and t-net fused ----------------
template <int PHASE>
__global__ __launch_bounds__(NTHREADS, 2)
void phase_kernel(const float* __restrict__ x,
                  const float* __restrict__ cond,
                  const float* __restrict__ b0g,
                  const float* __restrict__ b1g,
                  const float* __restrict__ W2g,
                  const float* __restrict__ b2g,
                  float* __restrict__ out) {
    extern __shared__ char smraw[];
    __nv_bfloat16* actH = (__nv_bfloat16*)smraw;        // 64 x 264 bf16
    __nv_bfloat16* actL = actH + NTOK * PITCH2;
    float* sArr = (float*)(actL + NTOK * PITCH2);       // 64
    float* tArr = sArr + NTOK;                          // 64
    float* w2sm = tArr + NTOK;                          // 256 (s | t)

    const int tid = threadIdx.x;
    const int lane = tid & 31;
    const int wid = tid >> 5;
    const int wnet = wid >> 2;                 // 0 = s-warp, 1 = t-warp
    const int w4 = wid & 3;
    const int n8base = w4 * 4;                 // 4 n8-tiles (32 outs within net)
    const int nbase = blockIdx.x * NTOK;
    const int b = nbase >> 12;

    uint32_t actH_s = (uint32_t)__cvta_generic_to_shared(actH);
    uint32_t actL_s = (uint32_t)__cvta_generic_to_shared(actL);
    uint32_t* actH_u = (uint32_t*)actH;
    uint32_t* actL_u = (uint32_t*)actL;

    const int r8 = lane & 7;
    const int gA = (lane >> 3) & 1;
    const int gB = lane >> 4;

    const int net = ((PHASE == 1) ? 0 : 2) + wnet;
    const int netColOff = wnet ? TOFF : 0;     // act col base for this warp's net (l>0)

    // ---- gather: 4 threads per token, 16 lf channels each ----
    {
        int tk = tid >> 2;
        int q4 = tid & 3;
        int n = nbase + tk;
        float zx, zy, zkeep;
        if (PHASE == 1) { zx = x[2 * n]; zy = x[2 * n + 1]; zkeep = zy; }
        else            { zx = out[2 * n]; zy = x[2 * n + 1]; zkeep = zx; }
        float ix = zx * 63.0f, iy = zy * 63.0f;
        float ix0 = floorf(ix), iy0 = floorf(iy);
        float wx1 = ix - ix0, wx0 = 1.0f - wx1;
        float wy1 = iy - iy0, wy0 = 1.0f - wy1;
        float acc[16];
#pragma unroll
        for (int c = 0; c < 16; c++) acc[c] = 0.0f;
#pragma unroll
        for (int corner = 0; corner < 4; corner++) {
            int dx = corner & 1, dy = corner >> 1;
            float xx = ix0 + (float)dx, yy = iy0 + (float)dy;
            if (xx >= 0.0f && xx <= 63.0f && yy >= 0.0f && yy <= 63.0f) {
                float wgt = (dx ? wx1 : wx0) * (dy ? wy1 : wy0);
                const float4* gp = (const float4*)(g_wT +
                    (((size_t)b * HDIM + (int)yy) * WDIM + (int)xx) * CDIM + q4 * 16);
#pragma unroll
                for (int q = 0; q < 4; q++) {
                    float4 v = gp[q];
                    acc[q * 4 + 0] += wgt * v.x;
                    acc[q * 4 + 1] += wgt * v.y;
                    acc[q * 4 + 2] += wgt * v.z;
                    acc[q * 4 + 3] += wgt * v.w;
                }
            }
        }
#pragma unroll
        for (int c = 0; c < 8; c++)
            split_store_pair(actH_u, actL_u, tk, q4 * 16 + 2 * c,
                             acc[2 * c], acc[2 * c + 1]);
        if (q4 == 0) {          // cond -> bf16 cols 64..79 (u32 32..39)
#pragma unroll
            for (int j = 0; j < 8; j++) {
                float c0 = cond[b * CONDD + 2 * j];
                float c1 = cond[b * CONDD + 2 * j + 1];
                split_store_pair(actH_u, actL_u, tk, 64 + 2 * j, c0, c1);
            }
        } else if (q4 == 1) {   // z at col 80, zeros 82..95
            split_store_pair(actH_u, actL_u, tk, 80, zkeep, 0.0f);
#pragma unroll
            for (int q = 41; q < 48; q++) {
                actH_u[tk * PITCH2_U32 + q] = 0u;
                actL_u[tk * PITCH2_U32 + q] = 0u;
            }
        }
    }
    // stage W2 for both nets
    if (tid < 2 * HID) {
        int wh = tid >> 7;
        int nn = tid & 127;
        w2sm[tid] = W2g[(((PHASE == 1) ? 0 : 2) + wh) * HID + nn];
    }
    __syncthreads();

    // ---- 4 fused layers: each warp computes its net's 32 outs over 64 toks ----
    for (int l = 0; l < 4; ++l) {
        const int img = net * 4 + l;
        const int ksteps = (l == 0) ? 6 : 8;
        const int aColBase = (l == 0) ? 0 : netColOff;   // layer0 reads shared comb
        const float* bias = (l == 0) ? (b0g + net * HID)
                                     : (b1g + (net * 3 + (l - 1)) * HID);

        float acc[4][4][4];
#pragma unroll
        for (int mi = 0; mi < 4; mi++)
#pragma unroll
            for (int t = 0; t < 4; t++)
#pragma unroll
                for (int q = 0; q < 4; q++) acc[mi][t][q] = 0.0f;

#pragma unroll 2
        for (int ks = 0; ks < ksteps; ++ks) {
            uint2 bh[4], bl[4];
#pragma unroll
            for (int t = 0; t < 4; t++) {
                int off = (((img * 8 + ks) * 16 + n8base + t) << 6) + lane * 2;
                bh[t] = *(const uint2*)&g_WfH[off];
                bl[t] = *(const uint2*)&g_WfL[off];
            }
            int colA = aColBase + ks * 16 + gB * 8;
#pragma unroll
            for (int mi = 0; mi < 4; mi++) {
                uint32_t aH[4], aL[4];
                uint32_t offA = (uint32_t)(((mi * 16 + r8 + gA * 8) * PITCH2 + colA) * 2);
                ldsm_x4(aH, actH_s + offA);
                ldsm_x4(aL, actL_s + offA);
#pragma unroll
                for (int t = 0; t < 4; t++) {
                    float* c4 = acc[mi][t];
                    mma_bf16(c4, aH, bh[t].x, bh[t].y);
                    mma_bf16(c4, aH, bl[t].x, bl[t].y);
                    mma_bf16(c4, aL, bh[t].x, bh[t].y);
                }
            }
        }
        __syncthreads();   // all act reads done before in-place overwrite

        // epilogue: bias + silu -> split bf16 -> own net's act region
#pragma unroll
        for (int t = 0; t < 4; t++) {
            int nn = n8base * 8 + t * 8 + (lane & 3) * 2;   // out index within net
            float2 bb = *(const float2*)&bias[nn];
            int cc = netColOff + nn;                        // act col
#pragma unroll
            for (int mi = 0; mi < 4; mi++) {
                int row0 = mi * 16 + (lane >> 2);
                float* d = acc[mi][t];
                split_store_pair(actH_u, actL_u, row0, cc,
                                 silu_f(d[0] + bb.x), silu_f(d[1] + bb.y));
                split_store_pair(actH_u, actL_u, row0 + 8, cc,
                                 silu_f(d[2] + bb.x), silu_f(d[3] + bb.y));
            }
        }
        __syncthreads();
    }

    // ---- final 128 -> 1 dots, s and t in parallel ----
    if (tid < 2 * NTOK) {
        int wh = tid >> 6;          // 0 = s, 1 = t
        int tk = tid & 63;
        int base = tk * PITCH2_U32 + (wh ? (TOFF >> 1) : 0);
        const float* w2 = w2sm + wh * HID;
        float sum = 0.0f;
#pragma unroll 8
        for (int i = 0; i < 64; ++i) {
            uint32_t hp = actH_u[base + i];
            uint32_t lp = actL_u[base + i];
            __nv_bfloat162 hv = *reinterpret_cast<__nv_bfloat162*>(&hp);
            __nv_bfloat162 lv = *reinterpret_cast<__nv_bfloat162*>(&lp);
            float v0 = __bfloat162float(hv.x) + __bfloat162float(lv.x);
            float v1 = __bfloat162float(hv.y) + __bfloat162float(lv.y);
            sum += v0 * w2[2 * i] + v1 * w2[2 * i + 1];
        }
        float* dst = wh ? tArr : sArr;
        dst[tk] = sum + b2g[((PHASE == 1) ? 0 : 2) + wh];
    }
    __syncthreads();

    // ---- coupling update + log_det ----
    if (tid < NTOK) {
        int n = nbase + tid;
        float s = tanhf(sArr[tid]) * S_MAX;
        float t = tArr[tid];
        float zold = (PHASE == 1) ? x[2 * n] : x[2 * n + 1];
        out[2 * n + ((PHASE == 1) ? 0 : 1)] = zold * expf(s) + t;
        sArr[tid] = s;
    }
    __syncthreads();
    if (tid < 32) {
        float v = sArr[tid] + sArr[tid + 32];
#pragma unroll
        for (int off = 16; off > 0; off >>= 1) v += __shfl_down_sync(0xffffffffu, v, off);
        if (tid == 0) atomicAdd(out + ZSIZE + b, v);
    }
}

// ---------------- launch ----------------
extern "C" void kernel_launch(void* const* d_in, const int* in_sizes, int n_in,
                              void* d_out, int out_size) {
    const float* x    = (const float*)d_in[0];
    const float* w    = (const float*)d_in[1];
    const float* cond = (const float*)d_in[2];
    const float* W0   = (const float*)d_in[3];
    const float* b0   = (const float*)d_in[4];
    const float* W1   = (const float*)d_in[5];
    const float* b1   = (const float*)d_in[6];
    const float* W2   = (const float*)d_in[7];
    const float* b2   = (const float*)d_in[8];
    float* out = (float*)d_out;

    const size_t smem = (size_t)(2 * NTOK * PITCH2) * 2 +      // actH, actL
                        (size_t)(2 * NTOK + 2 * HID) * 4;      // sArr, tArr, w2sm
    cudaFuncSetAttribute(phase_kernel<1>, cudaFuncAttributeMaxDynamicSharedMemorySize, (int)smem);
    cudaFuncSetAttribute(phase_kernel<2>, cudaFuncAttributeMaxDynamicSharedMemorySize, (int)smem);

    prep_kernel<<<1024, NTHREADS>>>(W0, W1, out);
    transpose_w_kernel<<<BDIM * HDIM, NTHREADS>>>(w);
    phase_kernel<1><<<NTOT / NTOK, NTHREADS, smem>>>(x, cond, b0, b1, W2, b2, out);
    phase_kernel<2><<<NTOT / NTOK, NTHREADS, smem>>>(x, cond, b0, b1, W2, b2, out);
}

// round 15
// speedup vs baseline: 1.2968x; 1.0498x over previous
#include <cuda_runtime.h>
#include <cuda_bf16.h>
#include <math.h>
#include <stdint.h>

#define BDIM 64
#define TDIM 4096
#define CDIM 64
#define HDIM 64
#define WDIM 64
#define CONDD 16
#define HID 128
#define INDIM 81
#define NTOK 64
#define NTHREADS 256
#define PITCH2 264            // act row pitch: s cols [0,128), t at [136,264)
#define PITCH2_U32 132
#define TOFF 136
#define CPITCH 104            // comb row pitch (bf16): rows 0-7 hit all 32 banks
#define CPITCH_U32 52
#define S_MAX 1.5f

#define NTOT (BDIM * TDIM)
#define ZSIZE ((size_t)NTOT * 2)

// ---------------- device scratch ----------------
__device__ float g_wT[(size_t)BDIM * HDIM * WDIM * CDIM];   // [b][y][x][c]
// B fragments in mma.sync lane order: [img(16)][ks(8)][n8(16)][lane(32)][reg(2)]
__device__ __align__(16) uint32_t g_WfH[16 * 8 * 16 * 64];
__device__ __align__(16) uint32_t g_WfL[16 * 8 * 16 * 64];

__device__ __forceinline__ float silu_f(float z) {
    return __fdividef(z, 1.0f + __expf(-z));
}
__device__ __forceinline__ void ldsm_x4(uint32_t d[4], uint32_t saddr) {
    asm volatile("ldmatrix.sync.aligned.m8n8.x4.shared.b16 {%0,%1,%2,%3}, [%4];\n"
        : "=r"(d[0]), "=r"(d[1]), "=r"(d[2]), "=r"(d[3]) : "r"(saddr));
}
__device__ __forceinline__ void mma_bf16(float c[4], const uint32_t a[4],
                                         uint32_t b0, uint32_t b1) {
    asm volatile(
        "mma.sync.aligned.m16n8k16.row.col.f32.bf16.bf16.f32 "
        "{%0,%1,%2,%3}, {%4,%5,%6,%7}, {%8,%9}, {%0,%1,%2,%3};\n"
        : "+f"(c[0]), "+f"(c[1]), "+f"(c[2]), "+f"(c[3])
        : "r"(a[0]), "r"(a[1]), "r"(a[2]), "r"(a[3]), "r"(b0), "r"(b1));
}
__device__ __forceinline__ void group_bar(int id) {
    asm volatile("bar.sync %0, 128;" :: "r"(id) : "memory");
}

__device__ __forceinline__ void split_store_pair_p(uint32_t* H, uint32_t* L, int pitch_u32,
                                                   int row, int n0, float a, float b) {
    __nv_bfloat16 ah = __float2bfloat16_rn(a);
    __nv_bfloat16 bh = __float2bfloat16_rn(b);
    float ar = a - __bfloat162float(ah);
    float br = b - __bfloat162float(bh);
    __nv_bfloat162 hp = __halves2bfloat162(ah, bh);
    __nv_bfloat162 lp = __halves2bfloat162(__float2bfloat16_rn(ar), __float2bfloat16_rn(br));
    H[row * pitch_u32 + (n0 >> 1)] = *reinterpret_cast<uint32_t*>(&hp);
    L[row * pitch_u32 + (n0 >> 1)] = *reinterpret_cast<uint32_t*>(&lp);
}

// ---------------- prep: weights -> mma fragment order (bf16 hi/lo) ----------
__global__ void prep_kernel(const float* __restrict__ W0,
                            const float* __restrict__ W1,
                            float* __restrict__ out) {
    int idx = blockIdx.x * blockDim.x + threadIdx.x;   // 0..262143
    if (idx < 16 * 8 * 16 * 64) {
        int reg  = idx & 1;
        int lane = (idx >> 1) & 31;
        int n8   = (idx >> 6) & 15;
        int ks   = (idx >> 10) & 7;
        int img  = idx >> 13;                          // net*4 + l
        int net = img >> 2, l = img & 3;
        int n  = n8 * 8 + (lane >> 2);
        int k0 = ks * 16 + (lane & 3) * 2 + reg * 8;
        float v0 = 0.0f, v1 = 0.0f;
        if (l == 0) {
            // act k-order: [lf(0..63) | cond(64..79) | z(80) | pad]
            if (k0 <= 80)     v0 = W0[(net * HID + n) * INDIM + ((k0 < 80) ? (k0 + 1) : 0)];
            if (k0 + 1 <= 80) v1 = W0[(net * HID + n) * INDIM + ((k0 + 1 < 80) ? (k0 + 2) : 0)];
        } else {
            int g = net * 3 + (l - 1);
            v0 = W1[(g * HID + n) * HID + k0];
            v1 = W1[(g * HID + n) * HID + k0 + 1];
        }
        __nv_bfloat16 h0 = __float2bfloat16_rn(v0);
        __nv_bfloat16 h1 = __float2bfloat16_rn(v1);
        __nv_bfloat162 hp = __halves2bfloat162(h0, h1);
        __nv_bfloat162 lp = __halves2bfloat162(
            __float2bfloat16_rn(v0 - __bfloat162float(h0)),
            __float2bfloat16_rn(v1 - __bfloat162float(h1)));
        g_WfH[idx] = *reinterpret_cast<uint32_t*>(&hp);
        g_WfL[idx] = *reinterpret_cast<uint32_t*>(&lp);
    }
    if (idx < BDIM) out[ZSIZE + idx] = 0.0f;
}

// ---------------- transpose w [B,C,H,W] -> g_wT [B,H,W,C] ----------------
__global__ void transpose_w_kernel(const float* __restrict__ w) {
    __shared__ float tile[64][65];
    int by = blockIdx.x;
    int b = by / HDIM, y = by % HDIM;
    int tid = threadIdx.x;
    for (int i = tid; i < 64 * 64; i += NTHREADS) {
        int c = i >> 6, xq = i & 63;
        tile[c][xq] = w[(((size_t)b * CDIM + c) * HDIM + y) * WDIM + xq];
    }
    __syncthreads();
    for (int i = tid; i < 64 * 64; i += NTHREADS) {
        int xq = i >> 6, c = i & 63;
        g_wT[(((size_t)b * HDIM + y) * WDIM + xq) * CDIM + c] = tile[c][xq];
    }
}

// ---------------- phase kernel: fused s/t nets, decoupled pipelines ---------
template <int PHASE>
__global__ __launch_bounds__(NTHREADS, 2)
void phase_kernel(const float* __restrict__ x,
                  const float* __restrict__ cond,
                  const float* __restrict__ b0g,
                  const float* __restrict__ b1g,
                  const float* __restrict__ W2g,
                  const float* __restrict__ b2g,
                  float* __restrict__ out) {
    extern __shared__ char smraw[];
    __nv_bfloat16* combH = (__nv_bfloat16*)smraw;         // 64 x 104
    __nv_bfloat16* combL = combH + NTOK * CPITCH;
    __nv_bfloat16* actH  = combL + NTOK * CPITCH;         // 64 x 264
    __nv_bfloat16* actL  = actH + NTOK * PITCH2;
    float* sArr = (float*)(actL + NTOK * PITCH2);         // 64
    float* tArr = sArr + NTOK;                            // 64
    float* w2sm = tArr + NTOK;                            // 256 (s | t)

    const int tid = threadIdx.x;
    const int lane = tid & 31;
    const int wid = tid >> 5;
    const int wnet = wid >> 2;                 // 0 = s-group, 1 = t-group
    const int w4 = wid & 3;
    const int n8base = w4 * 4;
    const int nbase = blockIdx.x * NTOK;
    const int b = nbase >> 12;

    uint32_t combH_s = (uint32_t)__cvta_generic_to_shared(combH);
    uint32_t combL_s = (uint32_t)__cvta_generic_to_shared(combL);
    uint32_t actH_s  = (uint32_t)__cvta_generic_to_shared(actH);
    uint32_t actL_s  = (uint32_t)__cvta_generic_to_shared(actL);
    uint32_t* combH_u = (uint32_t*)combH;
    uint32_t* combL_u = (uint32_t*)combL;
    uint32_t* actH_u = (uint32_t*)actH;
    uint32_t* actL_u = (uint32_t*)actL;

    const int r8 = lane & 7;
    const int gA = (lane >> 3) & 1;
    const int gB = lane >> 4;

    const int base_net = (PHASE == 1) ? 0 : 2;
    const int net = base_net + wnet;
    const int netColOff = wnet ? TOFF : 0;

    // ---- gather: 4 threads per token, 16 lf channels each -> comb ----
    {
        int tk = tid >> 2;
        int q4 = tid & 3;
        int n = nbase + tk;
        float zx, zy, zkeep;
        if (PHASE == 1) { zx = x[2 * n]; zy = x[2 * n + 1]; zkeep = zy; }
        else            { zx = out[2 * n]; zy = x[2 * n + 1]; zkeep = zx; }
        float ix = zx * 63.0f, iy = zy * 63.0f;
        float ix0 = floorf(ix), iy0 = floorf(iy);
        float wx1 = ix - ix0, wx0 = 1.0f - wx1;
        float wy1 = iy - iy0, wy0 = 1.0f - wy1;
        float acc[16];
#pragma unroll
        for (int c = 0; c < 16; c++) acc[c] = 0.0f;
#pragma unroll
        for (int corner = 0; corner < 4; corner++) {
            int dx = corner & 1, dy = corner >> 1;
            float xx = ix0 + (float)dx, yy = iy0 + (float)dy;
            if (xx >= 0.0f && xx <= 63.0f && yy >= 0.0f && yy <= 63.0f) {
                float wgt = (dx ? wx1 : wx0) * (dy ? wy1 : wy0);
                const float4* gp = (const float4*)(g_wT +
                    (((size_t)b * HDIM + (int)yy) * WDIM + (int)xx) * CDIM + q4 * 16);
#pragma unroll
                for (int q = 0; q < 4; q++) {
                    float4 v = gp[q];
                    acc[q * 4 + 0] += wgt * v.x;
                    acc[q * 4 + 1] += wgt * v.y;
                    acc[q * 4 + 2] += wgt * v.z;
                    acc[q * 4 + 3] += wgt * v.w;
                }
            }
        }
#pragma unroll
        for (int c = 0; c < 8; c++)
            split_store_pair_p(combH_u, combL_u, CPITCH_U32, tk, q4 * 16 + 2 * c,
                               acc[2 * c], acc[2 * c + 1]);
        if (q4 == 0) {
#pragma unroll
            for (int j = 0; j < 8; j++) {
                float c0 = cond[b * CONDD + 2 * j];
                float c1 = cond[b * CONDD + 2 * j + 1];
                split_store_pair_p(combH_u, combL_u, CPITCH_U32, tk, 64 + 2 * j, c0, c1);
            }
        } else if (q4 == 1) {
            split_store_pair_p(combH_u, combL_u, CPITCH_U32, tk, 80, zkeep, 0.0f);
#pragma unroll
            for (int q = 41; q < 48; q++) {
                combH_u[tk * CPITCH_U32 + q] = 0u;
                combL_u[tk * CPITCH_U32 + q] = 0u;
            }
        }
    }
    if (tid < 2 * HID) {
        int wh = tid >> 7;
        w2sm[tid] = W2g[(base_net + wh) * HID + (tid & 127)];
    }
    if (tid < NTOK) { sArr[tid] = 0.0f; tArr[tid] = 0.0f; }
    __syncthreads();

    // ---- 4 layers; group-local barriers only ----
    for (int l = 0; l < 4; ++l) {
        const int img = net * 4 + l;
        const int ksteps = (l == 0) ? 6 : 8;
        const float* bias = (l == 0) ? (b0g + net * HID)
                                     : (b1g + (net * 3 + (l - 1)) * HID);

        float acc[4][4][4];
#pragma unroll
        for (int mi = 0; mi < 4; mi++)
#pragma unroll
            for (int t = 0; t < 4; t++)
#pragma unroll
                for (int q = 0; q < 4; q++) acc[mi][t][q] = 0.0f;

#pragma unroll 2
        for (int ks = 0; ks < ksteps; ++ks) {
            uint2 bh[4], bl[4];
#pragma unroll
            for (int t = 0; t < 4; t++) {
                int off = (((img * 8 + ks) * 16 + n8base + t) << 6) + lane * 2;
                bh[t] = *(const uint2*)&g_WfH[off];
                bl[t] = *(const uint2*)&g_WfL[off];
            }
#pragma unroll
            for (int mi = 0; mi < 4; mi++) {
                uint32_t aH[4], aL[4];
                if (l == 0) {
                    int colA = ks * 16 + gB * 8;
                    uint32_t offA = (uint32_t)(((mi * 16 + r8 + gA * 8) * CPITCH + colA) * 2);
                    ldsm_x4(aH, combH_s + offA);
                    ldsm_x4(aL, combL_s + offA);
                } else {
                    int colA = netColOff + ks * 16 + gB * 8;
                    uint32_t offA = (uint32_t)(((mi * 16 + r8 + gA * 8) * PITCH2 + colA) * 2);
                    ldsm_x4(aH, actH_s + offA);
                    ldsm_x4(aL, actL_s + offA);
                }
#pragma unroll
                for (int t = 0; t < 4; t++) {
                    float* c4 = acc[mi][t];
                    mma_bf16(c4, aH, bh[t].x, bh[t].y);
                    mma_bf16(c4, aH, bl[t].x, bl[t].y);
                    mma_bf16(c4, aL, bh[t].x, bh[t].y);
                }
            }
        }

        if (l < 3) {
            if (l > 0) group_bar(1 + wnet);   // group's act reads done
            // epilogue: bias + silu -> split bf16 -> own act region
#pragma unroll
            for (int t = 0; t < 4; t++) {
                int nn = n8base * 8 + t * 8 + (lane & 3) * 2;
                float2 bb = *(const float2*)&bias[nn];
                int cc = netColOff + nn;
#pragma unroll
                for (int mi = 0; mi < 4; mi++) {
                    int row0 = mi * 16 + (lane >> 2);
                    float* d = acc[mi][t];
                    split_store_pair_p(actH_u, actL_u, PITCH2_U32, row0, cc,
                                       silu_f(d[0] + bb.x), silu_f(d[1] + bb.y));
                    split_store_pair_p(actH_u, actL_u, PITCH2_U32, row0 + 8, cc,
                                       silu_f(d[2] + bb.x), silu_f(d[3] + bb.y));
                }
            }
            group_bar(1 + wnet);              // writes visible to group
        } else {
            // ---- layer 3: fused dot epilogue (no act writes) ----
            float pA[4], pB[4];
#pragma unroll
            for (int mi = 0; mi < 4; mi++) { pA[mi] = 0.0f; pB[mi] = 0.0f; }
            const float* w2 = w2sm + wnet * HID;
#pragma unroll
            for (int t = 0; t < 4; t++) {
                int nn = n8base * 8 + t * 8 + (lane & 3) * 2;
                float2 bb = *(const float2*)&bias[nn];
                float2 ww = *(const float2*)&w2[nn];
#pragma unroll
                for (int mi = 0; mi < 4; mi++) {
                    float* d = acc[mi][t];
                    pA[mi] += silu_f(d[0] + bb.x) * ww.x + silu_f(d[1] + bb.y) * ww.y;
                    pB[mi] += silu_f(d[2] + bb.x) * ww.x + silu_f(d[3] + bb.y) * ww.y;
                }
            }
            float* dst = wnet ? tArr : sArr;
#pragma unroll
            for (int mi = 0; mi < 4; mi++) {
                pA[mi] += __shfl_xor_sync(0xffffffffu, pA[mi], 1);
                pA[mi] += __shfl_xor_sync(0xffffffffu, pA[mi], 2);
                pB[mi] += __shfl_xor_sync(0xffffffffu, pB[mi], 1);
                pB[mi] += __shfl_xor_sync(0xffffffffu, pB[mi], 2);
                if ((lane & 3) == 0) {
                    int row = mi * 16 + (lane >> 2);
                    atomicAdd(&dst[row], pA[mi]);
                    atomicAdd(&dst[row + 8], pB[mi]);
                }
            }
        }
    }
    __syncthreads();   // both groups' dot atomics visible

    // ---- coupling update + log_det ----
    if (tid < NTOK) {
        int n = nbase + tid;
        float s = tanhf(sArr[tid] + b2g[base_net]) * S_MAX;
        float t = tArr[tid] + b2g[base_net + 1];
        float zold = (PHASE == 1) ? x[2 * n] : x[2 * n + 1];
        out[2 * n + ((PHASE == 1) ? 0 : 1)] = zold * expf(s) + t;
        sArr[tid] = s;
    }
    __syncthreads();
    if (tid < 32) {
        float v = sArr[tid] + sArr[tid + 32];
#pragma unroll
        for (int off = 16; off > 0; off >>= 1) v += __shfl_down_sync(0xffffffffu, v, off);
        if (tid == 0) atomicAdd(out + ZSIZE + b, v);
    }
}

// ---------------- launch ----------------
extern "C" void kernel_launch(void* const* d_in, const int* in_sizes, int n_in,
                              void* d_out, int out_size) {
    const float* x    = (const float*)d_in[0];
    const float* w    = (const float*)d_in[1];
    const float* cond = (const float*)d_in[2];
    const float* W0   = (const float*)d_in[3];
    const float* b0   = (const float*)d_in[4];
    const float* W1   = (const float*)d_in[5];
    const float* b1   = (const float*)d_in[6];
    const float* W2   = (const float*)d_in[7];
    const float* b2   = (const float*)d_in[8];
    float* out = (float*)d_out;

    const size_t smem = (size_t)(2 * NTOK * CPITCH) * 2 +      // combH/L
                        (size_t)(2 * NTOK * PITCH2) * 2 +      // actH/L
                        (size_t)(2 * NTOK + 2 * HID) * 4;      // sArr, tArr, w2sm
    cudaFuncSetAttribute(phase_kernel<1>, cudaFuncAttributeMaxDynamicSharedMemorySize, (int)smem);
    cudaFuncSetAttribute(phase_kernel<2>, cudaFuncAttributeMaxDynamicSharedMemorySize, (int)smem);

    prep_kernel<<<1024, NTHREADS>>>(W0, W1, out);
    transpose_w_kernel<<<BDIM * HDIM, NTHREADS>>>(w);
    phase_kernel<1><<<NTOT / NTOK, NTHREADS, smem>>>(x, cond, b0, b1, W2, b2, out);
    phase_kernel<2><<<NTOT / NTOK, NTHREADS, smem>>>(x, cond, b0, b1, W2, b2, out);
}